// round 9
// baseline (speedup 1.0000x reference)
#include <cuda_runtime.h>
#include <cstdint>
#include <cstddef>

#define B_   32
#define T_   4096
#define D_   512
#define G_   8
#define OUT_ 512
#define CHUNK 256  // tokens per reduce block
#define DT_  128   // d-chunk per gemm block

// Static device scratch (no allocations allowed).
__device__ float g_sums[B_ * G_ * D_];   // 512 KB
__device__ int   g_counts[B_ * G_];
__device__ int   g_mask_u8;              // 1 if key_padding_mask is byte-packed

// ---------------------------------------------------------------------------
// Kernel 0: zero scratch, init out with bias, and (block 0) detect mask width.
// Byte-packed random bools make most 32-bit words > 1; int32 bools are 0/1.
// ---------------------------------------------------------------------------
__global__ void zero_kernel(const float* __restrict__ bias, float* __restrict__ out,
                            const unsigned int* __restrict__ mask_words) {
    if (blockIdx.x == 0) {
        int any = 0;
        for (int i = threadIdx.x; i < 2048; i += 256)
            if (mask_words[i] > 1u) any = 1;
        any = __syncthreads_or(any);
        if (threadIdx.x == 0) g_mask_u8 = any;
    }
    int idx = blockIdx.x * blockDim.x + threadIdx.x;
    int stride = gridDim.x * blockDim.x;
    for (int i = idx; i < B_ * G_ * D_; i += stride) g_sums[i] = 0.0f;
    for (int i = idx; i < B_ * G_ * OUT_; i += stride)
        out[i] = bias[i & (G_ * OUT_ - 1)];              // i % (G*OUT), layout [b,g,o]
    if (idx < B_ * G_) g_counts[idx] = 0;
}

// ---------------------------------------------------------------------------
// Kernel 1: segmented masked sum — group-sorted runs, branch-free hot loop.
// grid = (T/CHUNK, B) = (16, 32) = 512 blocks, 128 threads.
// Valid tokens are compacted into smem SORTED BY GROUP (count -> scan ->
// scatter). Accumulation then walks each group's run with batches of 8
// unconditional LDG.128s into a single float4 accumulator (no switch, no
// per-item branch). Tail of each run uses one clamped-index masked batch.
// Padded tokens (~50%) are skipped entirely -> ~half the HBM traffic.
// ---------------------------------------------------------------------------
__global__ void __launch_bounds__(128)
reduce_kernel(const float* __restrict__ batch,
              const int* __restrict__ types,
              const void* __restrict__ pad_raw) {
    __shared__ int s_code[CHUNK];          // group or -1 per token
    __shared__ int s_idx[CHUNK];           // tokens sorted by group
    __shared__ int s_cnt[G_];
    __shared__ int s_start[G_ + 1];
    __shared__ int s_ofs[G_];

    const int tid = threadIdx.x;
    const int b   = blockIdx.y;
    const int t0  = blockIdx.x * CHUNK;
    const bool u8 = (g_mask_u8 != 0);
    const unsigned char* pad8 = (const unsigned char*)pad_raw;
    const int*           padi = (const int*)pad_raw;

    if (tid < G_) s_cnt[tid] = 0;
    __syncthreads();

    // pass 1: decode + count
    for (int i = tid; i < CHUNK; i += 128) {
        int t = t0 + i;
        int p = u8 ? (int)pad8[(size_t)b * T_ + t] : padi[(size_t)b * T_ + t];
        int c = -1;
        if (!p) { c = types[t]; atomicAdd(&s_cnt[c], 1); }
        s_code[i] = c;
    }
    __syncthreads();

    // exclusive scan over 8 groups
    if (tid == 0) {
        int a = 0;
        #pragma unroll
        for (int g = 0; g < G_; ++g) { s_start[g] = a; s_ofs[g] = a; a += s_cnt[g]; }
        s_start[G_] = a;
    }
    __syncthreads();

    // pass 2: scatter tokens into group-sorted order
    for (int i = tid; i < CHUNK; i += 128) {
        int c = s_code[i];
        if (c >= 0) s_idx[atomicAdd(&s_ofs[c], 1)] = i;
    }
    __syncthreads();

    const float4* rows = reinterpret_cast<const float4*>(batch)
                       + ((size_t)b * T_ + t0) * (D_ / 4) + tid;

#define LOAD8                                                                  \
        float4 v0 = rows[(size_t)s_idx[i+0] * (D_/4)];                         \
        float4 v1 = rows[(size_t)s_idx[i+1] * (D_/4)];                         \
        float4 v2 = rows[(size_t)s_idx[i+2] * (D_/4)];                         \
        float4 v3 = rows[(size_t)s_idx[i+3] * (D_/4)];                         \
        float4 v4 = rows[(size_t)s_idx[i+4] * (D_/4)];                         \
        float4 v5 = rows[(size_t)s_idx[i+5] * (D_/4)];                         \
        float4 v6 = rows[(size_t)s_idx[i+6] * (D_/4)];                         \
        float4 v7 = rows[(size_t)s_idx[i+7] * (D_/4)];
#define TREE4(X)                                                               \
        a.X += (((v0.X + v1.X) + (v2.X + v3.X)) +                              \
                ((v4.X + v5.X) + (v6.X + v7.X)));

    float* gbase = g_sums + ((size_t)b * G_) * D_ + tid * 4;

    #pragma unroll
    for (int g = 0; g < G_; ++g) {
        int i = s_start[g];
        const int e = s_start[g + 1];
        if (i >= e) continue;                       // empty group (uniform branch)
        float4 a = {0.f, 0.f, 0.f, 0.f};

        for (; i + 8 <= e; i += 8) {                // full batches: branch-free body
            LOAD8
            TREE4(x) TREE4(y) TREE4(z) TREE4(w)
        }
        if (i < e) {                                 // one masked tail batch
            const int n = e - i;                     // 1..7
            float4 w0, w1, w2, w3, w4, w5, w6, w7;
            w0 = rows[(size_t)s_idx[i] * (D_/4)];
            w1 = rows[(size_t)s_idx[i + (1 < n ? 1 : n-1)] * (D_/4)];
            w2 = rows[(size_t)s_idx[i + (2 < n ? 2 : n-1)] * (D_/4)];
            w3 = rows[(size_t)s_idx[i + (3 < n ? 3 : n-1)] * (D_/4)];
            w4 = rows[(size_t)s_idx[i + (4 < n ? 4 : n-1)] * (D_/4)];
            w5 = rows[(size_t)s_idx[i + (5 < n ? 5 : n-1)] * (D_/4)];
            w6 = rows[(size_t)s_idx[i + (6 < n ? 6 : n-1)] * (D_/4)];
            w7 = rows[(size_t)s_idx[i + (7 < n ? 7 : n-1)] * (D_/4)];
            a.x += w0.x; a.y += w0.y; a.z += w0.z; a.w += w0.w;
            if (1 < n) { a.x += w1.x; a.y += w1.y; a.z += w1.z; a.w += w1.w; }
            if (2 < n) { a.x += w2.x; a.y += w2.y; a.z += w2.z; a.w += w2.w; }
            if (3 < n) { a.x += w3.x; a.y += w3.y; a.z += w3.z; a.w += w3.w; }
            if (4 < n) { a.x += w4.x; a.y += w4.y; a.z += w4.z; a.w += w4.w; }
            if (5 < n) { a.x += w5.x; a.y += w5.y; a.z += w5.z; a.w += w5.w; }
            if (6 < n) { a.x += w6.x; a.y += w6.y; a.z += w6.z; a.w += w6.w; }
        }

        // flush this group's partial (spread-address REDG)
        float* d = gbase + g * D_;
        atomicAdd(d + 0, a.x); atomicAdd(d + 1, a.y);
        atomicAdd(d + 2, a.z); atomicAdd(d + 3, a.w);
    }
#undef TREE4
#undef LOAD8

    if (tid < G_ && s_cnt[tid] > 0) atomicAdd(&g_counts[b * G_ + tid], s_cnt[tid]);
}

// ---------------------------------------------------------------------------
// Kernel 2: means + per-group GEMM (split-D x4, smem cross-lane reduction,
// then accumulate into bias-initialized out).
// grid = (OUT/64, G, D/128) = (8, 8, 4) = 256 blocks, 256 threads.
// Thread = 1 output column x 32 batches. The 4 d-lanes combine through smem
// before the global atomic -> 2048 REDGs per block instead of 8192.
// ---------------------------------------------------------------------------
__global__ void __launch_bounds__(256)
gemm_kernel(const float* __restrict__ W, float* __restrict__ out) {
    // phase 1 uses first 128*36 floats as transposed means; phase 2 reuses the
    // whole buffer for the cross-lane reduction (layout stride 131: conflict-free).
    __shared__ __align__(16) float s_buf[64 * 131 + 32];   // ~33 KB
    __shared__ float s_inv[B_];

    const int tid = threadIdx.x;
    const int oc0 = blockIdx.x * 64;
    const int g   = blockIdx.y;
    const int d0  = blockIdx.z * DT_;

    if (tid < B_) {
        int cnt = g_counts[tid * G_ + g];
        s_inv[tid] = (cnt > 0) ? 1.0f / (float)cnt : 0.0f;   // empty group -> mean 0
    }
    __syncthreads();

    // stage means transposed: s_buf[d*36 + b]  (coalesced g_sums reads)
    for (int idx = tid; idx < B_ * DT_; idx += 256) {
        int bb = idx >> 7;          // 0..31
        int d  = idx & (DT_ - 1);   // 0..127
        s_buf[d * 36 + bb] = g_sums[((size_t)bb * G_ + g) * D_ + d0 + d] * s_inv[bb];
    }
    __syncthreads();

    const int olane = tid & 63;     // output column within tile
    const int dbase = tid >> 6;     // 0..3 d-lane
    const int o     = oc0 + olane;

    float acc[32];
    #pragma unroll
    for (int i = 0; i < 32; ++i) acc[i] = 0.0f;

    const float* Wp = W + ((size_t)g * D_ + d0 + dbase) * OUT_ + o;
    #pragma unroll 8
    for (int k = 0; k < 32; ++k) {
        float w = Wp[(size_t)k * 4 * OUT_];
        const float* mrow = &s_buf[(dbase + 4 * k) * 36];
        #pragma unroll
        for (int q = 0; q < 8; ++q) {
            float4 m = *(const float4*)(mrow + q * 4);   // broadcast across warp
            acc[q * 4 + 0] += w * m.x;
            acc[q * 4 + 1] += w * m.y;
            acc[q * 4 + 2] += w * m.z;
            acc[q * 4 + 3] += w * m.w;
        }
    }
    __syncthreads();   // staging buffer is dead; reuse for reduction

    // write partials: s_buf[olane*131 + dbase*32 + bb]  (131 stride: no conflicts)
    #pragma unroll
    for (int bb = 0; bb < 32; ++bb)
        s_buf[olane * 131 + dbase * 32 + bb] = acc[bb];
    __syncthreads();

    // each thread combines 4 d-lanes for 8 outputs, then one REDG per output
    #pragma unroll
    for (int q = 0; q < 8; ++q) {
        int oi = tid * 8 + q;       // 0..2047
        int oo = oi >> 5;           // 0..63
        int bb = oi & 31;           // 0..31
        const float* p = &s_buf[oo * 131 + bb];
        float sum = p[0] + p[32] + p[64] + p[96];
        atomicAdd(&out[((size_t)bb * G_ + g) * OUT_ + oc0 + oo], sum);
    }
}

// ---------------------------------------------------------------------------
extern "C" void kernel_launch(void* const* d_in, const int* in_sizes, int n_in,
                              void* d_out, int out_size) {
    const float* batch = (const float*)d_in[0];          // [B,T,D] f32
    const float* W     = (const float*)d_in[1];          // [G,D,OUT] f32
    const float* bias  = (const float*)d_in[2];          // [G,OUT] f32
    const int*   types = (const int*)d_in[3];            // [T] i32
    const void*  pad   = d_in[4];                        // [B,T] bool (width detected)
    float* out = (float*)d_out;                          // [B,G,OUT] f32

    zero_kernel<<<256, 256>>>(bias, out, (const unsigned int*)pad);
    reduce_kernel<<<dim3(T_ / CHUNK, B_), 128>>>(batch, types, pad);
    gemm_kernel<<<dim3(OUT_ / 64, G_, D_ / DT_), 256>>>(W, out);
}

// round 10
// speedup vs baseline: 1.2118x; 1.2118x over previous
#include <cuda_runtime.h>
#include <cstdint>
#include <cstddef>

#define B_   32
#define T_   4096
#define D_   512
#define G_   8
#define OUT_ 512
#define CHUNK 256  // tokens per reduce block
#define DT_  128   // d-chunk per gemm block

// Static device scratch (no allocations allowed).
__device__ float g_sums[B_ * G_ * D_];   // 512 KB
__device__ int   g_counts[B_ * G_];
__device__ int   g_mask_u8;              // 1 if key_padding_mask is byte-packed

// ---------------------------------------------------------------------------
// Kernel 0: vectorized init — zero g_sums, out = bias, counts = 0; block 0
// additionally detects mask width (byte-packed random bools make most 32-bit
// words > 1; int32 bools are always 0/1). One float4 store per thread.
// grid = 512 x 128 = 65536 threads = 32768 (g_sums) + 32768 (out) float4s.
// ---------------------------------------------------------------------------
__global__ void __launch_bounds__(128)
zero_kernel(const float* __restrict__ bias, float* __restrict__ out,
            const unsigned int* __restrict__ mask_words) {
    if (blockIdx.x == 0) {
        int any = 0;
        for (int i = threadIdx.x; i < 2048; i += 128)
            if (mask_words[i] > 1u) any = 1;
        any = __syncthreads_or(any);
        if (threadIdx.x == 0) g_mask_u8 = any;
    }
    const int idx = blockIdx.x * 128 + threadIdx.x;
    const int NS4 = B_ * G_ * D_ / 4;    // 32768 float4s of g_sums
    if (idx < NS4) {
        reinterpret_cast<float4*>(g_sums)[idx] = make_float4(0.f, 0.f, 0.f, 0.f);
    } else {
        int j = idx - NS4;               // 0..32767 float4s of out
        reinterpret_cast<float4*>(out)[j] =
            reinterpret_cast<const float4*>(bias)[j & (G_ * OUT_ / 4 - 1)];
    }
    if (idx < B_ * G_) g_counts[idx] = 0;
}

// ---------------------------------------------------------------------------
// Kernel 1: segmented masked sum, MLP-8 (R7-proven version, unchanged).
// grid = (T/CHUNK, B) = (16, 32) = 512 blocks, 128 threads.
// Valid tokens compacted into smem (padded to a multiple of 8 with group=-1
// sentinels), then the main loop issues 8 UNCONDITIONAL LDG.128s before any
// accumulation -> deep MLP. Padded tokens (~50%) are skipped entirely.
// ---------------------------------------------------------------------------
__global__ void __launch_bounds__(128)
reduce_kernel(const float* __restrict__ batch,
              const int* __restrict__ types,
              const void* __restrict__ pad_raw) {
    __shared__ int s_idx[CHUNK + 8];
    __shared__ int s_grp[CHUNK + 8];
    __shared__ int s_cnt[G_];
    __shared__ int s_nv;

    const int tid = threadIdx.x;
    const int b   = blockIdx.y;
    const int t0  = blockIdx.x * CHUNK;
    const bool u8 = (g_mask_u8 != 0);
    const unsigned char* pad8 = (const unsigned char*)pad_raw;
    const int*           padi = (const int*)pad_raw;

    if (tid < G_) s_cnt[tid] = 0;
    if (tid == 0) s_nv = 0;
    __syncthreads();
    for (int i = tid; i < CHUNK; i += 128) {
        int t = t0 + i;
        int p = u8 ? (int)pad8[(size_t)b * T_ + t] : padi[(size_t)b * T_ + t];
        if (!p) {
            int g = types[t];
            int slot = atomicAdd(&s_nv, 1);
            s_idx[slot] = i;
            s_grp[slot] = g;
            atomicAdd(&s_cnt[g], 1);
        }
    }
    __syncthreads();
    const int nv  = s_nv;
    const int nvp = (nv + 7) & ~7;
    if (tid == 0) {
        for (int j = nv; j < nvp; ++j) { s_idx[j] = 0; s_grp[j] = -1; }
    }
    __syncthreads();

    float4 a0 = {0,0,0,0}, a1 = {0,0,0,0}, a2 = {0,0,0,0}, a3 = {0,0,0,0};
    float4 a4 = {0,0,0,0}, a5 = {0,0,0,0}, a6 = {0,0,0,0}, a7 = {0,0,0,0};

    const float4* rows = reinterpret_cast<const float4*>(batch)
                       + ((size_t)b * T_ + t0) * (D_ / 4) + tid;

#define ACC(A, V) { A.x += V.x; A.y += V.y; A.z += V.z; A.w += V.w; }
#define SWACC(g, V)                                                            \
    switch (g) {                                                               \
        case 0: ACC(a0, V); break;  case 1: ACC(a1, V); break;                 \
        case 2: ACC(a2, V); break;  case 3: ACC(a3, V); break;                 \
        case 4: ACC(a4, V); break;  case 5: ACC(a5, V); break;                 \
        case 6: ACC(a6, V); break;  case 7: ACC(a7, V); break;                 \
        default: break;                                                        \
    }

    for (int i = 0; i < nvp; i += 8) {
        int j0 = s_idx[i+0], j1 = s_idx[i+1], j2 = s_idx[i+2], j3 = s_idx[i+3];
        int j4 = s_idx[i+4], j5 = s_idx[i+5], j6 = s_idx[i+6], j7 = s_idx[i+7];
        int c0 = s_grp[i+0], c1 = s_grp[i+1], c2 = s_grp[i+2], c3 = s_grp[i+3];
        int c4 = s_grp[i+4], c5 = s_grp[i+5], c6 = s_grp[i+6], c7 = s_grp[i+7];
        // 8 unconditional loads, issued before any consumer -> MLP 8
        float4 v0 = rows[(size_t)j0 * (D_/4)];
        float4 v1 = rows[(size_t)j1 * (D_/4)];
        float4 v2 = rows[(size_t)j2 * (D_/4)];
        float4 v3 = rows[(size_t)j3 * (D_/4)];
        float4 v4 = rows[(size_t)j4 * (D_/4)];
        float4 v5 = rows[(size_t)j5 * (D_/4)];
        float4 v6 = rows[(size_t)j6 * (D_/4)];
        float4 v7 = rows[(size_t)j7 * (D_/4)];
        SWACC(c0, v0) SWACC(c1, v1) SWACC(c2, v2) SWACC(c3, v3)
        SWACC(c4, v4) SWACC(c5, v5) SWACC(c6, v6) SWACC(c7, v7)
    }
#undef SWACC
#undef ACC

    // flush: spread-address scalar atomics, skipping empty groups
    float* base = g_sums + ((size_t)b * G_) * D_ + tid * 4;
#define FLUSH(gi, A)                                                           \
    if (s_cnt[gi] > 0) {                                                       \
        float* d = base + (gi) * D_;                                           \
        atomicAdd(d + 0, A.x); atomicAdd(d + 1, A.y);                          \
        atomicAdd(d + 2, A.z); atomicAdd(d + 3, A.w);                          \
    }
    FLUSH(0, a0) FLUSH(1, a1) FLUSH(2, a2) FLUSH(3, a3)
    FLUSH(4, a4) FLUSH(5, a5) FLUSH(6, a6) FLUSH(7, a7)
#undef FLUSH
    if (tid < G_ && s_cnt[tid] > 0) atomicAdd(&g_counts[b * G_ + tid], s_cnt[tid]);
}

// ---------------------------------------------------------------------------
// Kernel 2: means + per-group GEMM (split-D x4 AND split-batch x2).
// grid = (16, G, D/128): x = (o-tile 0..7) * 2 + (batch-half 0..1) -> 512
// blocks, 256 threads. Thread = 1 output column x 16 batches. Same total
// atomic count as the R7 version (each block emits half the elements at the
// same 4-way d-redundancy); double the resident blocks hides W-load latency.
// ---------------------------------------------------------------------------
__global__ void __launch_bounds__(256)
gemm_kernel(const float* __restrict__ W, float* __restrict__ out) {
    __shared__ __align__(16) float s_m[DT_ * 20];   // 10 KB, stride 20 (80B, 16B-aligned)
    __shared__ float s_inv[16];

    const int tid = threadIdx.x;
    const int oc0 = (blockIdx.x >> 1) * 64;
    const int b0  = (blockIdx.x & 1) * 16;
    const int g   = blockIdx.y;
    const int d0  = blockIdx.z * DT_;

    if (tid < 16) {
        int cnt = g_counts[(b0 + tid) * G_ + g];
        s_inv[tid] = (cnt > 0) ? 1.0f / (float)cnt : 0.0f;   // empty group -> mean 0
    }
    __syncthreads();

    // stage means transposed: s_m[d*20 + b]  (coalesced g_sums reads)
    for (int idx = tid; idx < 16 * DT_; idx += 256) {
        int bb = idx >> 7;          // 0..15
        int d  = idx & (DT_ - 1);   // 0..127
        s_m[d * 20 + bb] = g_sums[((size_t)(b0 + bb) * G_ + g) * D_ + d0 + d] * s_inv[bb];
    }
    __syncthreads();

    const int o     = oc0 + (tid & 63);
    const int dbase = tid >> 6;     // 0..3

    float acc[16];
    #pragma unroll
    for (int i = 0; i < 16; ++i) acc[i] = 0.0f;

    const float* Wp = W + ((size_t)g * D_ + d0 + dbase) * OUT_ + o;
    #pragma unroll 8
    for (int k = 0; k < 32; ++k) {
        float w = Wp[(size_t)k * 4 * OUT_];
        const float* mrow = &s_m[(dbase + 4 * k) * 20];
        #pragma unroll
        for (int q = 0; q < 4; ++q) {
            float4 m = *(const float4*)(mrow + q * 4);   // broadcast across warp
            acc[q * 4 + 0] += w * m.x;
            acc[q * 4 + 1] += w * m.y;
            acc[q * 4 + 2] += w * m.z;
            acc[q * 4 + 3] += w * m.w;
        }
    }

    #pragma unroll
    for (int bb = 0; bb < 16; ++bb)
        atomicAdd(&out[((size_t)(b0 + bb) * G_ + g) * OUT_ + o], acc[bb]);
}

// ---------------------------------------------------------------------------
extern "C" void kernel_launch(void* const* d_in, const int* in_sizes, int n_in,
                              void* d_out, int out_size) {
    const float* batch = (const float*)d_in[0];          // [B,T,D] f32
    const float* W     = (const float*)d_in[1];          // [G,D,OUT] f32
    const float* bias  = (const float*)d_in[2];          // [G,OUT] f32
    const int*   types = (const int*)d_in[3];            // [T] i32
    const void*  pad   = d_in[4];                        // [B,T] bool (width detected)
    float* out = (float*)d_out;                          // [B,G,OUT] f32

    zero_kernel<<<512, 128>>>(bias, out, (const unsigned int*)pad);
    reduce_kernel<<<dim3(T_ / CHUNK, B_), 128>>>(batch, types, pad);
    gemm_kernel<<<dim3(16, G_, D_ / DT_), 256>>>(W, out);
}

// round 12
// speedup vs baseline: 1.3142x; 1.0845x over previous
#include <cuda_runtime.h>
#include <cstdint>
#include <cstddef>

#define B_    32
#define T_    4096
#define D_    512
#define G_    8
#define OUT_  512
#define CHUNK 256                 // tokens per reduce block
#define NC_   (T_ / CHUNK)        // 16 chunks
#define DT_   128                 // d-chunk per gemm block

// Static device scratch (no allocations allowed).
__device__ float g_part[B_ * NC_ * G_ * D_];   // 8 MB: per-(b,chunk) group partials
__device__ int   g_cnt_part[B_ * NC_ * G_];    // per-(b,chunk) group counts
__device__ float g_means[B_ * G_ * D_];        // 512 KB

// ---------------------------------------------------------------------------
// Kernel 1: segmented masked sum -> PRIVATE partials (no atomics, no zeroing).
// grid = (NC_, B) = (16, 32) = 512 blocks, 128 threads.
// Mask width (u8 vs i32 bool) detected per-block from the first 256 mask
// words (1 KB: in-bounds under both interpretations; byte-packed random bools
// make some word > 1, int32 bools never do). Valid tokens compacted into smem
// (padded to a multiple of 8 with group=-1 sentinels), then the main loop
// issues 8 UNCONDITIONAL LDG.128s before any accumulation -> deep MLP.
// Padded tokens (~50%) are skipped entirely. Flush = plain coalesced stores.
// ---------------------------------------------------------------------------
__global__ void __launch_bounds__(128)
reduce_kernel(const float* __restrict__ batch,
              const int* __restrict__ types,
              const void* __restrict__ pad_raw) {
    __shared__ int s_idx[CHUNK + 8];
    __shared__ int s_grp[CHUNK + 8];
    __shared__ int s_cnt[G_];
    __shared__ int s_nv;

    const int tid = threadIdx.x;
    const int b   = blockIdx.y;
    const int cnk = blockIdx.x;
    const int t0  = cnk * CHUNK;
    const unsigned char* pad8 = (const unsigned char*)pad_raw;
    const int*           padi = (const int*)pad_raw;

    // per-block mask-width detect (same 1KB region for every block; L2 hit)
    int any = 0;
    const unsigned int* mw = (const unsigned int*)pad_raw;
    for (int i = tid; i < 256; i += 128)
        if (mw[i] > 1u) any = 1;
    const bool u8 = __syncthreads_or(any);

    if (tid < G_) s_cnt[tid] = 0;
    if (tid == 0) s_nv = 0;
    __syncthreads();
    for (int i = tid; i < CHUNK; i += 128) {
        int t = t0 + i;
        int p = u8 ? (int)pad8[(size_t)b * T_ + t] : padi[(size_t)b * T_ + t];
        if (!p) {
            int g = types[t];
            int slot = atomicAdd(&s_nv, 1);
            s_idx[slot] = i;
            s_grp[slot] = g;
            atomicAdd(&s_cnt[g], 1);
        }
    }
    __syncthreads();
    const int nv  = s_nv;
    const int nvp = (nv + 7) & ~7;
    if (tid == 0) {
        for (int j = nv; j < nvp; ++j) { s_idx[j] = 0; s_grp[j] = -1; }
    }
    __syncthreads();

    float4 a0 = {0,0,0,0}, a1 = {0,0,0,0}, a2 = {0,0,0,0}, a3 = {0,0,0,0};
    float4 a4 = {0,0,0,0}, a5 = {0,0,0,0}, a6 = {0,0,0,0}, a7 = {0,0,0,0};

    const float4* rows = reinterpret_cast<const float4*>(batch)
                       + ((size_t)b * T_ + t0) * (D_ / 4) + tid;

#define ACC(A, V) { A.x += V.x; A.y += V.y; A.z += V.z; A.w += V.w; }
#define SWACC(g, V)                                                            \
    switch (g) {                                                               \
        case 0: ACC(a0, V); break;  case 1: ACC(a1, V); break;                 \
        case 2: ACC(a2, V); break;  case 3: ACC(a3, V); break;                 \
        case 4: ACC(a4, V); break;  case 5: ACC(a5, V); break;                 \
        case 6: ACC(a6, V); break;  case 7: ACC(a7, V); break;                 \
        default: break;                                                        \
    }

    for (int i = 0; i < nvp; i += 8) {
        int j0 = s_idx[i+0], j1 = s_idx[i+1], j2 = s_idx[i+2], j3 = s_idx[i+3];
        int j4 = s_idx[i+4], j5 = s_idx[i+5], j6 = s_idx[i+6], j7 = s_idx[i+7];
        int c0 = s_grp[i+0], c1 = s_grp[i+1], c2 = s_grp[i+2], c3 = s_grp[i+3];
        int c4 = s_grp[i+4], c5 = s_grp[i+5], c6 = s_grp[i+6], c7 = s_grp[i+7];
        // 8 unconditional loads, issued before any consumer -> MLP 8
        float4 v0 = rows[(size_t)j0 * (D_/4)];
        float4 v1 = rows[(size_t)j1 * (D_/4)];
        float4 v2 = rows[(size_t)j2 * (D_/4)];
        float4 v3 = rows[(size_t)j3 * (D_/4)];
        float4 v4 = rows[(size_t)j4 * (D_/4)];
        float4 v5 = rows[(size_t)j5 * (D_/4)];
        float4 v6 = rows[(size_t)j6 * (D_/4)];
        float4 v7 = rows[(size_t)j7 * (D_/4)];
        SWACC(c0, v0) SWACC(c1, v1) SWACC(c2, v2) SWACC(c3, v3)
        SWACC(c4, v4) SWACC(c5, v5) SWACC(c6, v6) SWACC(c7, v7)
    }
#undef SWACC
#undef ACC

    // flush: plain coalesced float4 stores into this block's private slice
    float4* dst = reinterpret_cast<float4*>(g_part)
                + ((size_t)(b * NC_ + cnk) * G_) * (D_ / 4) + tid;
    dst[0 * (D_/4)] = a0;  dst[1 * (D_/4)] = a1;
    dst[2 * (D_/4)] = a2;  dst[3 * (D_/4)] = a3;
    dst[4 * (D_/4)] = a4;  dst[5 * (D_/4)] = a5;
    dst[6 * (D_/4)] = a6;  dst[7 * (D_/4)] = a7;
    if (tid < G_) g_cnt_part[(b * NC_ + cnk) * G_ + tid] = s_cnt[tid];
}

// ---------------------------------------------------------------------------
// Kernel 2: finalize — collapse chunk partials into means, and seed out=bias
// for gemm's atomic accumulation. grid = (B*G) = 256 blocks, 128 threads.
// ---------------------------------------------------------------------------
__global__ void __launch_bounds__(128)
finalize_kernel(const float* __restrict__ bias, float* __restrict__ out) {
    const int tid = threadIdx.x;
    const int b   = blockIdx.x >> 3;
    const int g   = blockIdx.x & 7;

    int cnt = 0;
    #pragma unroll
    for (int c = 0; c < NC_; ++c) cnt += g_cnt_part[(b * NC_ + c) * G_ + g];
    const float inv = (cnt > 0) ? 1.0f / (float)cnt : 0.0f;   // empty group -> 0

    const float4* part = reinterpret_cast<const float4*>(g_part);
    float4 acc = {0.f, 0.f, 0.f, 0.f};
    #pragma unroll
    for (int c = 0; c < NC_; ++c) {
        float4 v = part[((size_t)(b * NC_ + c) * G_ + g) * (D_ / 4) + tid];
        acc.x += v.x; acc.y += v.y; acc.z += v.z; acc.w += v.w;
    }
    acc.x *= inv; acc.y *= inv; acc.z *= inv; acc.w *= inv;
    reinterpret_cast<float4*>(g_means)[((size_t)b * G_ + g) * (D_ / 4) + tid] = acc;

    // seed out[b][g][:] = bias[g][:]  (OUT_=512 floats -> 128 float4s)
    reinterpret_cast<float4*>(out)[((size_t)b * G_ + g) * (OUT_ / 4) + tid] =
        reinterpret_cast<const float4*>(bias)[g * (OUT_ / 4) + tid];
}

// ---------------------------------------------------------------------------
// Kernel 3: per-group GEMM (split-D x4, split-batch x2), atomic accumulate
// into bias-seeded out. grid = (16, G, D/128) = 512 blocks, 256 threads.
// Thread = 1 output column x 16 batches.
// ---------------------------------------------------------------------------
__global__ void __launch_bounds__(256)
gemm_kernel(const float* __restrict__ W, float* __restrict__ out) {
    __shared__ __align__(16) float s_m[DT_ * 20];   // 10 KB, stride 20

    const int tid = threadIdx.x;
    const int oc0 = (blockIdx.x >> 1) * 64;
    const int b0  = (blockIdx.x & 1) * 16;
    const int g   = blockIdx.y;
    const int d0  = blockIdx.z * DT_;

    // stage means transposed: s_m[d*20 + b]  (coalesced g_means reads)
    for (int idx = tid; idx < 16 * DT_; idx += 256) {
        int bb = idx >> 7;          // 0..15
        int d  = idx & (DT_ - 1);   // 0..127
        s_m[d * 20 + bb] = g_means[((size_t)(b0 + bb) * G_ + g) * D_ + d0 + d];
    }
    __syncthreads();

    const int o     = oc0 + (tid & 63);
    const int dbase = tid >> 6;     // 0..3

    float acc[16];
    #pragma unroll
    for (int i = 0; i < 16; ++i) acc[i] = 0.0f;

    const float* Wp = W + ((size_t)g * D_ + d0 + dbase) * OUT_ + o;
    #pragma unroll 8
    for (int k = 0; k < 32; ++k) {
        float w = Wp[(size_t)k * 4 * OUT_];
        const float* mrow = &s_m[(dbase + 4 * k) * 20];
        #pragma unroll
        for (int q = 0; q < 4; ++q) {
            float4 m = *(const float4*)(mrow + q * 4);   // broadcast across warp
            acc[q * 4 + 0] += w * m.x;
            acc[q * 4 + 1] += w * m.y;
            acc[q * 4 + 2] += w * m.z;
            acc[q * 4 + 3] += w * m.w;
        }
    }

    #pragma unroll
    for (int bb = 0; bb < 16; ++bb)
        atomicAdd(&out[((size_t)(b0 + bb) * G_ + g) * OUT_ + o], acc[bb]);
}

// ---------------------------------------------------------------------------
extern "C" void kernel_launch(void* const* d_in, const int* in_sizes, int n_in,
                              void* d_out, int out_size) {
    const float* batch = (const float*)d_in[0];          // [B,T,D] f32
    const float* W     = (const float*)d_in[1];          // [G,D,OUT] f32
    const float* bias  = (const float*)d_in[2];          // [G,OUT] f32
    const int*   types = (const int*)d_in[3];            // [T] i32
    const void*  pad   = d_in[4];                        // [B,T] bool (width detected)
    float* out = (float*)d_out;                          // [B,G,OUT] f32

    reduce_kernel<<<dim3(NC_, B_), 128>>>(batch, types, pad);
    finalize_kernel<<<B_ * G_, 128>>>(bias, out);
    gemm_kernel<<<dim3(16, G_, D_ / DT_), 256>>>(W, out);
}